// round 11
// baseline (speedup 1.0000x reference)
#include <cuda_runtime.h>
#include <cstdint>
#include <cstddef>

// Problem constants
#define BB 8
#define SS 1024
#define DD 1024
#define HH 8
#define DHD 128
#define MM (BB * SS)   // 8192 rows

// ---------------------------------------------------------------------------
// Scratch (device-global: allocation inside kernel_launch is forbidden)
// ---------------------------------------------------------------------------
__device__ float g_Q[(size_t)MM * DD];
__device__ float g_K[(size_t)MM * DD];
__device__ float g_V[(size_t)MM * DD];
__device__ float g_qmask[MM];

// ---------------------------------------------------------------------------
// Helpers
// ---------------------------------------------------------------------------
// Round-to-nearest tf32 (RNA). Unbiased — raw truncation (RZ) biases every
// GEMM output ~1e-3 low, which breaches the rel_err gate when stacked.
__device__ __forceinline__ float to_tf32(float x) {
    uint32_t u;
    asm("cvt.rna.tf32.f32 %0, %1;" : "=r"(u) : "f"(x));
    return __uint_as_float(u);
}

// D = A(16x8) * B(8x8) + D, tf32 inputs (must be pre-rounded), fp32 accumulate
__device__ __forceinline__ void mma8(float* c, const float* a, const float* b) {
    asm volatile(
        "mma.sync.aligned.m16n8k8.row.col.f32.tf32.tf32.f32 "
        "{%0,%1,%2,%3}, {%4,%5,%6,%7}, {%8,%9}, {%0,%1,%2,%3};\n"
        : "+f"(c[0]), "+f"(c[1]), "+f"(c[2]), "+f"(c[3])
        : "r"(__float_as_uint(a[0])), "r"(__float_as_uint(a[1])),
          "r"(__float_as_uint(a[2])), "r"(__float_as_uint(a[3])),
          "r"(__float_as_uint(b[0])), "r"(__float_as_uint(b[1])));
}

__device__ __forceinline__ void cp16(float* smem_dst, const float* gsrc) {
    uint32_t s = (uint32_t)__cvta_generic_to_shared(smem_dst);
    asm volatile("cp.async.cg.shared.global [%0], [%1], 16;\n"
                 :: "r"(s), "l"(gsrc));
}
#define CP_COMMIT() asm volatile("cp.async.commit_group;\n" ::: "memory")
#define CP_WAIT(n)  asm volatile("cp.async.wait_group %0;\n" :: "n"(n) : "memory")

// ---------------------------------------------------------------------------
// qmask[b,s] = sign(|sum_d queries[b,s,d]|) in {0,1}
// Warp-per-row: no smem, no block barriers. 1024 CTAs x 8 warps.
// Lane l reads float4 at col 4*l + 128*it -> fully coalesced 512B/warp/iter.
// ---------------------------------------------------------------------------
__global__ __launch_bounds__(256) void qmask_kernel(const float* __restrict__ q) {
    const int warp = threadIdx.x >> 5, lane = threadIdx.x & 31;
    const int row  = blockIdx.x * 8 + warp;        // 0..8191
    const float* p = q + (size_t)row * DD;
    float s = 0.f;
#pragma unroll
    for (int it = 0; it < 8; it++) {
        float4 v = *(const float4*)(p + it * 128 + lane * 4);
        s += (v.x + v.y) + (v.z + v.w);
    }
#pragma unroll
    for (int o = 16; o > 0; o >>= 1)
        s += __shfl_xor_sync(0xffffffffu, s, o);
    if (lane == 0) g_qmask[row] = (s != 0.0f) ? 1.0f : 0.0f;
}

// ---------------------------------------------------------------------------
// Fused Q/K/V projections: dst_z = relu(X_z @ W_z^T + bias_z) rounded to tf32
// blockIdx.z in {0,1,2} selects (X, W, bias, dst). One launch, 1536 CTAs ->
// 5.2 waves instead of 3 x 1.73 waves (tail waste ~27% -> ~4%).
// 3-buffer cp.async ring (prefetch distance 2), K-stage depth 32.
// RNA conversion applied at fragment load (smem holds raw fp32).
// grid: (1024/128, 8192/128, 3), block 256, dyn smem 110592 B
// ---------------------------------------------------------------------------
__global__ __launch_bounds__(256) void proj_kernel(
    const float* __restrict__ Xq, const float* __restrict__ Xk,
    const float* __restrict__ Xv,
    const float* __restrict__ Wq, const float* __restrict__ Wk,
    const float* __restrict__ Wv,
    const float* __restrict__ bq, const float* __restrict__ bk,
    const float* __restrict__ bv,
    float* __restrict__ dq, float* __restrict__ dk, float* __restrict__ dv)
{
    constexpr int SP = 36;               // padded row stride (floats)
    constexpr int TILE = 128 * SP;       // one 128x32 tile (padded)
    extern __shared__ float psm[];       // [3 buf][X tile | W tile]

    const float* X;  const float* W;  const float* bias;  float* dst;
    if (blockIdx.z == 0)      { X = Xq; W = Wq; bias = bq; dst = dq; }
    else if (blockIdx.z == 1) { X = Xk; W = Wk; bias = bk; dst = dk; }
    else                      { X = Xv; W = Wv; bias = bv; dst = dv; }

    const int tid  = threadIdx.x;
    const int lane = tid & 31, warp = tid >> 5;
    const int wm = (warp >> 1) * 32;     // warp row offset (4 warp-rows x 32)
    const int wn = (warp & 1) * 64;      // warp col offset (2 warp-cols x 64)
    const int qr = lane >> 2, qc = lane & 3;
    const int rowBase = blockIdx.y * 128;
    const int colBase = blockIdx.x * 128;

    const int lr = tid >> 3;             // 0..31
    const int lc = (tid & 7) * 4;        // 0,4,..,28

    float c[2][8][4];
#pragma unroll
    for (int i = 0; i < 2; i++)
#pragma unroll
        for (int j = 0; j < 8; j++)
#pragma unroll
            for (int k = 0; k < 4; k++) c[i][j][k] = 0.f;

    auto load_stage = [&](int buf, int k0) {
        float* sx = psm + buf * 2 * TILE;
        float* sw = sx + TILE;
#pragma unroll
        for (int i = 0; i < 4; i++) {
            const int r = lr + 32 * i;
            cp16(sx + r * SP + lc, X + (size_t)(rowBase + r) * DD + k0 + lc);
            cp16(sw + r * SP + lc, W + (size_t)(colBase + r) * DD + k0 + lc);
        }
    };

    load_stage(0, 0);
    CP_COMMIT();
    load_stage(1, 32);
    CP_COMMIT();

    constexpr int NSTAGE = DD / 32;      // 32
    for (int s = 0; s < NSTAGE; s++) {
        if (s + 2 < NSTAGE) {
            load_stage((s + 2) % 3, (s + 2) * 32);
            CP_COMMIT();
            CP_WAIT(2);                  // stage s landed (s+1, s+2 in flight)
        } else if (s + 1 < NSTAGE) {
            CP_WAIT(1);                  // stage s landed (s+1 in flight)
        } else {
            CP_WAIT(0);
        }
        __syncthreads();

        const float* sX = psm + (s % 3) * 2 * TILE;
        const float* sW = sX + TILE;
#pragma unroll
        for (int ks = 0; ks < 4; ks++) {
            const int k8 = ks * 8;
            float a[2][4];
#pragma unroll
            for (int mt = 0; mt < 2; mt++) {
                const int rb = wm + mt * 16 + qr;
                a[mt][0] = to_tf32(sX[rb * SP + k8 + qc]);
                a[mt][1] = to_tf32(sX[(rb + 8) * SP + k8 + qc]);
                a[mt][2] = to_tf32(sX[rb * SP + k8 + 4 + qc]);
                a[mt][3] = to_tf32(sX[(rb + 8) * SP + k8 + 4 + qc]);
            }
#pragma unroll
            for (int nt = 0; nt < 8; nt++) {
                const int cb = wn + nt * 8 + qr;
                float b2[2] = { to_tf32(sW[cb * SP + k8 + qc]),
                                to_tf32(sW[cb * SP + k8 + 4 + qc]) };
                mma8(c[0][nt], a[0], b2);
                mma8(c[1][nt], a[1], b2);
            }
        }
        __syncthreads();
    }

    // epilogue: + bias, relu, round to tf32 (RNA) so the attention MMAs see
    // exact-tf32 inputs (HW truncation then drops nothing)
#pragma unroll
    for (int mt = 0; mt < 2; mt++) {
#pragma unroll
        for (int nt = 0; nt < 8; nt++) {
            const int rg = rowBase + wm + mt * 16 + qr;
            const int cg = colBase + wn + nt * 8 + qc * 2;
            const float b0 = bias[cg], b1 = bias[cg + 1];
            float2 v0 = make_float2(to_tf32(fmaxf(c[mt][nt][0] + b0, 0.f)),
                                    to_tf32(fmaxf(c[mt][nt][1] + b1, 0.f)));
            float2 v1 = make_float2(to_tf32(fmaxf(c[mt][nt][2] + b0, 0.f)),
                                    to_tf32(fmaxf(c[mt][nt][3] + b1, 0.f)));
            *(float2*)(dst + (size_t)rg * DD + cg) = v0;
            *(float2*)(dst + (size_t)(rg + 8) * DD + cg) = v1;
        }
    }
}

// ---------------------------------------------------------------------------
// Fused attention: scores + attn_score write + online softmax + P@V
// Q/K/V gmem values are exact tf32 -> raw cp.async tiles are MMA-safe.
// K chunk 0 prefetched with Q (sKV has no prior readers then).
// grid: (S/128 q-tiles, H*B), block 256, dynamic smem 200KB
// ---------------------------------------------------------------------------
__global__ __launch_bounds__(256, 1) void attn_kernel(
    float* __restrict__ out, float* __restrict__ attn)
{
    constexpr int SPAD = 132;
    extern __shared__ float sm[];
    float* sQ   = sm;                   // 128 x 132
    float* sKV  = sQ  + 128 * SPAD;     // 128 x 132 (K then V, reused)
    float* sS   = sKV + 128 * SPAD;     // 128 x 132 (scores / P)
    float* s_l  = sS  + 128 * SPAD;     // 128
    float* s_m  = s_l + 128;            // 128
    float* s_fac= s_m + 128;            // 128
    float* s_qm = s_fac + 128;          // 128

    const int tid  = threadIdx.x;
    const int lane = tid & 31, warp = tid >> 5;
    const int wm = (warp >> 1) * 32;
    const int wn = (warp & 1) * 64;
    const int qr = lane >> 2, qc = lane & 3;

    const int qtile = blockIdx.x;       // 0..7
    const int bh    = blockIdx.y;       // 0..63  == h*B + b
    const int h = bh / BB, b = bh % BB;
    const int qrow0 = qtile * 128;

    // async copy of one 128x128 tile (head-sliced) into padded smem
    auto copy_tile = [&](const float* __restrict__ src, int rowbase, float* dst) {
#pragma unroll
        for (int it = 0; it < 16; it++) {
            const int l4  = it * 256 + tid;
            const int row = l4 >> 5;
            const int c4  = (l4 & 31) * 4;
            cp16(dst + row * SPAD + c4,
                 src + (size_t)(b * SS + rowbase + row) * DD + h * DHD + c4);
        }
    };

    // Prefetch Q and K(0) together — sKV has no readers before chunk 0,
    // so this is race-free and hides the first K-tile latency under init.
    copy_tile(g_Q, qrow0, sQ);
    copy_tile(g_K, 0, sKV);
    CP_COMMIT();

    for (int r = tid; r < 128; r += 256) {
        s_m[r]  = -3.4e38f;
        s_l[r]  = 0.f;
        s_qm[r] = g_qmask[b * SS + qrow0 + r];
    }

    float co[2][8][4];
#pragma unroll
    for (int i = 0; i < 2; i++)
#pragma unroll
        for (int j = 0; j < 8; j++)
#pragma unroll
            for (int k = 0; k < 4; k++) co[i][j][k] = 0.f;

    const float SC = 0.088388347648318447f;   // 1/sqrt(128)

    for (int chunk = 0; chunk < 8; chunk++) {
        if (chunk > 0) {
            __syncthreads();                   // prior PV readers done with sKV
            copy_tile(g_K, chunk * 128, sKV);
            CP_COMMIT();
        }
        CP_WAIT(0);                            // K (and Q on chunk 0) landed
        __syncthreads();

        // S = Q @ K^T
        float cs[2][8][4];
#pragma unroll
        for (int i = 0; i < 2; i++)
#pragma unroll
            for (int j = 0; j < 8; j++)
#pragma unroll
                for (int k = 0; k < 4; k++) cs[i][j][k] = 0.f;

#pragma unroll
        for (int ks = 0; ks < 16; ks++) {
            const int k8 = ks * 8;
            float a[2][4];
#pragma unroll
            for (int mt = 0; mt < 2; mt++) {
                const int rb = wm + mt * 16 + qr;
                a[mt][0] = sQ[rb * SPAD + k8 + qc];
                a[mt][1] = sQ[(rb + 8) * SPAD + k8 + qc];
                a[mt][2] = sQ[rb * SPAD + k8 + 4 + qc];
                a[mt][3] = sQ[(rb + 8) * SPAD + k8 + 4 + qc];
            }
#pragma unroll
            for (int nt = 0; nt < 8; nt++) {
                const int nb = wn + nt * 8 + qr;
                float b2[2] = { sKV[nb * SPAD + k8 + qc],
                                sKV[nb * SPAD + k8 + 4 + qc] };
                mma8(cs[0][nt], a[0], b2);
                mma8(cs[1][nt], a[1], b2);
            }
        }

        // stage scaled scores into sS
#pragma unroll
        for (int mt = 0; mt < 2; mt++) {
#pragma unroll
            for (int nt = 0; nt < 8; nt++) {
                const int row = wm + mt * 16 + qr;
                const int col = wn + nt * 8 + qc * 2;
                *(float2*)(sS + row * SPAD + col) =
                    make_float2(cs[mt][nt][0] * SC, cs[mt][nt][1] * SC);
                *(float2*)(sS + (row + 8) * SPAD + col) =
                    make_float2(cs[mt][nt][2] * SC, cs[mt][nt][3] * SC);
            }
        }
        __syncthreads();                       // all K-mma reads done, sS ready

        // V tile copy runs async under the whole softmax phase
        copy_tile(g_V, chunk * 128, sKV);      // overwrites K
        CP_COMMIT();

        // phase1: attn_score write (coalesced) + row max
        const size_t sbase = (size_t)bh * SS * SS + (size_t)qrow0 * SS + chunk * 128;
#pragma unroll
        for (int it = 0; it < 16; it++) {
            const int l4  = it * 256 + tid;
            const int row = l4 >> 5;
            const int c4  = (l4 & 31) * 4;
            float4 v = *(float4*)(sS + row * SPAD + c4);
            const float qm = s_qm[row];
            v.x *= qm; v.y *= qm; v.z *= qm; v.w *= qm;
            *(float4*)(attn + sbase + (size_t)row * SS + c4) = v;
        }
        const int r2 = tid >> 1, hf = tid & 1;
        float mx = -3.4e38f;
        {
            const float* srow = sS + r2 * SPAD + hf * 64;
#pragma unroll
            for (int j = 0; j < 64; j++) mx = fmaxf(mx, srow[j]);
        }
        mx = fmaxf(mx, __shfl_xor_sync(0xffffffffu, mx, 1));
        const float m_old = s_m[r2];
        const float m_new = fmaxf(m_old, mx);

        // RACE FIX: phase1 reads other threads' sS rows (gmem score write);
        // phase2 overwrites sS rows in place. Cross-warp read/write separation.
        __syncthreads();

        // phase2: exp, row sums, P in place (RNA tf32 — unbiased for PV mma)
        float sum = 0.f;
        {
            float* prow = sS + r2 * SPAD + hf * 64;
#pragma unroll
            for (int j = 0; j < 64; j++) {
                const float p = __expf(prow[j] - m_new);
                sum += p;
                prow[j] = to_tf32(p);
            }
        }
        sum += __shfl_xor_sync(0xffffffffu, sum, 1);
        const float fac = __expf(m_old - m_new);
        if (hf == 0) {
            s_l[r2]   = s_l[r2] * fac + sum;
            s_m[r2]   = m_new;
            s_fac[r2] = fac;
        }
        CP_WAIT(0);                            // V landed
        __syncthreads();

        // phase3: rescale O accum, then O += P @ V
#pragma unroll
        for (int mt = 0; mt < 2; mt++) {
            const float f0 = s_fac[wm + mt * 16 + qr];
            const float f1 = s_fac[wm + mt * 16 + 8 + qr];
#pragma unroll
            for (int nt = 0; nt < 8; nt++) {
                co[mt][nt][0] *= f0; co[mt][nt][1] *= f0;
                co[mt][nt][2] *= f1; co[mt][nt][3] *= f1;
            }
        }
#pragma unroll
        for (int ks = 0; ks < 16; ks++) {
            const int k8 = ks * 8;
            float a[2][4];
#pragma unroll
            for (int mt = 0; mt < 2; mt++) {
                const int rb = wm + mt * 16 + qr;
                a[mt][0] = sS[rb * SPAD + k8 + qc];
                a[mt][1] = sS[(rb + 8) * SPAD + k8 + qc];
                a[mt][2] = sS[rb * SPAD + k8 + 4 + qc];
                a[mt][3] = sS[(rb + 8) * SPAD + k8 + 4 + qc];
            }
#pragma unroll
            for (int nt = 0; nt < 8; nt++) {
                const int nb = wn + nt * 8 + qr;
                float b2[2] = { sKV[(k8 + qc) * SPAD + nb],
                                sKV[(k8 + 4 + qc) * SPAD + nb] };
                mma8(co[0][nt], a[0], b2);
                mma8(co[1][nt], a[1], b2);
            }
        }
    }

    __syncthreads();
    // stage O = (O / l) * qmask into sS, then coalesced write
#pragma unroll
    for (int mt = 0; mt < 2; mt++) {
#pragma unroll
        for (int nt = 0; nt < 8; nt++) {
            const int row = wm + mt * 16 + qr;
            const int col = wn + nt * 8 + qc * 2;
            const float r0 = s_qm[row]     / s_l[row];
            const float r1 = s_qm[row + 8] / s_l[row + 8];
            *(float2*)(sS + row * SPAD + col) =
                make_float2(co[mt][nt][0] * r0, co[mt][nt][1] * r0);
            *(float2*)(sS + (row + 8) * SPAD + col) =
                make_float2(co[mt][nt][2] * r1, co[mt][nt][3] * r1);
        }
    }
    __syncthreads();
#pragma unroll
    for (int it = 0; it < 16; it++) {
        const int l4  = it * 256 + tid;
        const int row = l4 >> 5;
        const int c4  = (l4 & 31) * 4;
        float4 v = *(float4*)(sS + row * SPAD + c4);
        *(float4*)(out + (size_t)(b * SS + qrow0 + row) * DD + h * DHD + c4) = v;
    }
}

// ---------------------------------------------------------------------------
// Launch
// ---------------------------------------------------------------------------
extern "C" void kernel_launch(void* const* d_in, const int* in_sizes, int n_in,
                              void* d_out, int out_size)
{
    (void)in_sizes; (void)n_in; (void)out_size;
    const float* q  = (const float*)d_in[0];
    const float* k  = (const float*)d_in[1];
    const float* v  = (const float*)d_in[2];
    const float* Wq = (const float*)d_in[3];
    const float* bq = (const float*)d_in[4];
    const float* Wk = (const float*)d_in[5];
    const float* bk = (const float*)d_in[6];
    const float* Wv = (const float*)d_in[7];
    const float* bv = (const float*)d_in[8];

    float *gq, *gk, *gv;
    cudaGetSymbolAddress((void**)&gq, g_Q);
    cudaGetSymbolAddress((void**)&gk, g_K);
    cudaGetSymbolAddress((void**)&gv, g_V);

    qmask_kernel<<<MM / 8, 256>>>(q);

    const int proj_smem = 3 * 2 * 128 * 36 * (int)sizeof(float); // 110592
    cudaFuncSetAttribute(proj_kernel,
                         cudaFuncAttributeMaxDynamicSharedMemorySize, proj_smem);
    dim3 pg(DD / 128, MM / 128, 3);      // z selects Q/K/V projection
    proj_kernel<<<pg, 256, proj_smem>>>(q, k, v, Wq, Wk, Wv,
                                        bq, bk, bv, gq, gk, gv);

    float* out  = (float*)d_out;
    float* attn = out + (size_t)BB * SS * DD;

    const int attn_smem = (3 * 128 * 132 + 4 * 128) * (int)sizeof(float); // 204800
    cudaFuncSetAttribute(attn_kernel,
                         cudaFuncAttributeMaxDynamicSharedMemorySize, attn_smem);
    attn_kernel<<<dim3(SS / 128, HH * BB), 256, attn_smem>>>(out, attn);
}